// round 2
// baseline (speedup 1.0000x reference)
#include <cuda_runtime.h>
#include <cstddef>

#define TT 8192
#define NT 512
#define EE 16   // elements per thread (TT / NT)

__device__ __forceinline__ float tanh_approx(float x) {
    float y;
    asm("tanh.approx.f32 %0, %1;" : "=f"(y) : "f"(x));
    return y;
}
__device__ __forceinline__ float sigmoid_f(float z) {
    return __fdividef(1.f, 1.f + __expf(-z));
}
__device__ __forceinline__ float softplus_f(float z) {
    // inputs here are O(±10); unstable form is fine in fp32 and matches jax to ~1e-7
    return __logf(1.f + __expf(z));
}

__global__ __launch_bounds__(NT, 1)
void voltage_kernel(const float* __restrict__ X, const float* __restrict__ SC,
                    const float* __restrict__ W1, const float* __restrict__ b1,
                    const float* __restrict__ W2, const float* __restrict__ b2,
                    float* __restrict__ out)
{
    __shared__ float sI[TT];
    __shared__ float sRed[32];
    __shared__ float sA[32];
    __shared__ float sB[32];
    __shared__ float sTmean;
    __shared__ float sU10;

    const int b    = blockIdx.x;
    const int tid  = threadIdx.x;
    const int lane = tid & 31;
    const int wid  = tid >> 5;
    const float* __restrict__ Xb = X + (size_t)b * TT * 3;

    // ---------- phase 1: coalesced load of I, Temp; I -> smem; Temp -> sum ----------
    float tsum = 0.f;
    #pragma unroll
    for (int k = 0; k < EE; ++k) {
        int i = k * NT + tid;
        const float* p = Xb + (size_t)i * 3;
        float Ic = __ldg(p + 1);
        float Tp = __ldg(p + 2);
        sI[i] = Ic;
        tsum += Tp;
    }
    // block reduce for Tmean (nanmean over NaN-free data == mean)
    #pragma unroll
    for (int o = 16; o > 0; o >>= 1) tsum += __shfl_down_sync(0xffffffffu, tsum, o);
    if (lane == 0) sRed[wid] = tsum;
    __syncthreads();
    if (tid < 32) {
        float v = (tid < NT / 32) ? sRed[tid] : 0.f;
        #pragma unroll
        for (int o = 16; o > 0; o >>= 1) v += __shfl_down_sync(0xffffffffu, v, o);
        if (tid == 0) sTmean = v * (1.f / (float)TT);
    }
    __syncthreads();
    const float Tmean = sTmean;
    const float Q  = __ldg(SC + 2 * b + 0);
    const float R0 = __ldg(SC + 2 * b + 1);

    // ---------- phase 2: per-thread local dSOC prefix (chunk-contiguous) ----------
    const int cs = tid * EE;
    float socArr[EE];
    float run = 0.f;
    {
        float tprev = 0.f, Iprev = 0.f;
        if (cs > 0) { tprev = __ldg(Xb + (size_t)(cs - 1) * 3); Iprev = sI[cs - 1]; }
        #pragma unroll 1
        for (int e = 0; e < EE; ++e) {
            int i = cs + e;
            float tcur = __ldg(Xb + (size_t)i * 3);
            float Ic   = sI[i];
            if (i > 0) run += (Ic + Iprev) * (tcur - tprev) * (1.f / 36000.f);
            socArr[e] = run;
            tprev = tcur; Iprev = Ic;
        }
    }
    // exclusive block scan of thread totals (float add)
    float inc = run;
    #pragma unroll
    for (int o = 1; o < 32; o <<= 1) {
        float y = __shfl_up_sync(0xffffffffu, inc, o);
        if (lane >= o) inc += y;
    }
    if (lane == 31) sRed[wid] = inc;
    __syncthreads();
    if (tid < 32) {
        float v = (tid < NT / 32) ? sRed[tid] : 0.f;
        #pragma unroll
        for (int o = 1; o < 32; o <<= 1) {
            float y = __shfl_up_sync(0xffffffffu, v, o);
            if (lane >= o) v += y;
        }
        sRed[tid] = v;   // inclusive warp totals
    }
    __syncthreads();
    const float warpOff = (wid > 0) ? sRed[wid - 1] : 0.f;
    const float socBase = Q * 0.2f + warpOff + (inc - run);   // Q/QN + exclusive prefix

    // ---------- weights: fold constant MLP inputs (R0, Tmean are per-batch consts) ----------
    float w10[6], c1r[6], w20[6], w21[6], w25[6], w26[6];
    #pragma unroll
    for (int j = 0; j < 6; ++j) {
        w10[j]   = __ldg(W1 + j);
        float w11 = __ldg(W1 + 6 + j);
        float w12 = __ldg(W1 + 12 + j);
        c1r[j] = fmaf(R0, w11, fmaf(Tmean, w12, __ldg(b1 + j)));
        w20[j] = __ldg(W2 + j * 7 + 0);
        w21[j] = __ldg(W2 + j * 7 + 1);
        w25[j] = __ldg(W2 + j * 7 + 5);
        w26[j] = __ldg(W2 + j * 7 + 6);
    }
    const float b20 = __ldg(b2 + 0), b21 = __ldg(b2 + 1);
    const float b25 = __ldg(b2 + 5), b26 = __ldg(b2 + 6);

    // ---------- phase 3: per-element MLP + OCV + affine transition (a,b) ----------
    float aArr[EE], bArr[EE], baseArr[EE];
    float At = 1.f, Bt = 0.f;
    #pragma unroll 1
    for (int e = 0; e < EE; ++e) {
        int i = cs + e;
        float soc = socBase + socArr[e];

        float h[6];
        #pragma unroll
        for (int j = 0; j < 6; ++j)
            h[j] = softplus_f(fmaf(soc, w10[j], c1r[j]));

        float p0 = b20, p1 = b21, p5 = b25, p6 = b26;
        #pragma unroll
        for (int j = 0; j < 6; ++j) {
            p0 = fmaf(h[j], w20[j], p0);
            p1 = fmaf(h[j], w21[j], p1);
            p5 = fmaf(h[j], w25[j], p5);
            p6 = fmaf(h[j], w26[j], p6);
        }
        float R1 = 0.04f * sigmoid_f(0.01f * p0);
        float C  = 1e-6f * sigmoid_f(0.01f * p1);
        float xx = fmaf(0.79764f, sigmoid_f(0.01f * p5), 0.04236f);
        float yy = fmaf(0.82504f, sigmoid_f(0.01f * p6), 0.023f);

        float Up = fmaf(fmaf(fmaf(fmaf(fmaf(-2.2166f, yy, 3.5146f), yy, -2.0843f),
                                 yy, 1.6225f), yy, -1.6518f), yy, 4.4167f)
                 - 4.f * __expf(fmaf(109.451f, yy, -100.006f));
        float Un = 0.063f + 0.8f * __expf(-75.f * (xx + 0.001f))
                 - 0.012f  * tanh_approx((xx - 0.127f) * 62.5f)
                 - 0.0118f * tanh_approx((xx - 0.155f) * 62.5f)
                 - 0.0035f * tanh_approx((xx - 0.22f)  * 50.f)
                 - 0.0095f * tanh_approx((xx - 0.19f)  * 76.923076923f)
                 - 0.0145f * tanh_approx((xx - 0.49f)  * 50.f)
                 - 0.08f   * tanh_approx((xx - 1.03f)  * 18.18181818f);
        float OCV = Up - Un;

        float Ii = sI[i];
        baseArr[e] = fmaf(Ii, R0, OCV);

        float a, bb;
        if (i < TT - 1) {
            float dtI = sI[i + 1] - Ii;           // dt = diff of I (sic, per reference)
            float eps = dtI * C;
            a  = 1.f - eps;
            bb = eps * R1 * Ii;
        } else { a = 1.f; bb = 0.f; }
        aArr[e] = a; bArr[e] = bb;
        Bt = fmaf(a, Bt, bb);
        At = a * At;

        if (i == 0) {
            float p2 = __ldg(b2 + 2);
            #pragma unroll
            for (int j = 0; j < 6; ++j) p2 = fmaf(h[j], __ldg(W2 + j * 7 + 2), p2);
            float OCV_U = fmaf(0.75f, sigmoid_f(0.01f * p2), 0.05f);
            sU10 = -OCV_U - Ii * R0;
        }
    }

    // ---------- phase 4: block affine-pair scan (exclusive) ----------
    float Ai = At, Bi = Bt;
    #pragma unroll
    for (int o = 1; o < 32; o <<= 1) {
        float pA = __shfl_up_sync(0xffffffffu, Ai, o);
        float pB = __shfl_up_sync(0xffffffffu, Bi, o);
        if (lane >= o) { Bi = fmaf(Ai, pB, Bi); Ai = Ai * pA; }
    }
    if (lane == 31) { sA[wid] = Ai; sB[wid] = Bi; }
    __syncthreads();
    if (tid < 32) {
        float vA = (tid < NT / 32) ? sA[tid] : 1.f;
        float vB = (tid < NT / 32) ? sB[tid] : 0.f;
        #pragma unroll
        for (int o = 1; o < 32; o <<= 1) {
            float pA = __shfl_up_sync(0xffffffffu, vA, o);
            float pB = __shfl_up_sync(0xffffffffu, vB, o);
            if (lane >= o) { vB = fmaf(vA, pB, vB); vA = vA * pA; }
        }
        sA[tid] = vA; sB[tid] = vB;
    }
    __syncthreads();
    float offA = 1.f, offB = 0.f;
    if (wid > 0) { offA = sA[wid - 1]; offB = sB[wid - 1]; }
    float eA = __shfl_up_sync(0xffffffffu, Ai, 1);
    float eB = __shfl_up_sync(0xffffffffu, Bi, 1);
    if (lane == 0) { eA = 1.f; eB = 0.f; }
    // G = eThread ∘ warpOffset   (warp offset applied first)
    float GA = eA * offA;
    float GB = fmaf(eA, offB, eB);
    float U1 = fmaf(GA, sU10, GB);

    // ---------- phase 5: emit ----------
    float* __restrict__ outb = out + (size_t)b * TT;
    #pragma unroll 1
    for (int e = 0; e < EE; ++e) {
        outb[cs + e] = baseArr[e] + U1;            // voltages[i] uses state BEFORE transition i
        U1 = fmaf(aArr[e], U1, bArr[e]);
    }
}

extern "C" void kernel_launch(void* const* d_in, const int* in_sizes, int n_in,
                              void* d_out, int out_size)
{
    const float* X  = (const float*)d_in[0];
    const float* SC = (const float*)d_in[1];
    const float* W1 = (const float*)d_in[2];
    const float* b1 = (const float*)d_in[3];
    const float* W2 = (const float*)d_in[4];
    const float* b2 = (const float*)d_in[5];
    float* out = (float*)d_out;

    int B = in_sizes[1] / 2;   // SC is (B, 2)
    voltage_kernel<<<B, NT>>>(X, SC, W1, b1, W2, b2, out);
}

// round 3
// speedup vs baseline: 1.6724x; 1.6724x over previous
#include <cuda_runtime.h>
#include <cstddef>

#define TT 8192
#define NT 512
#define EE 16   // elements per thread (TT / NT)

__device__ __forceinline__ float tanh_approx(float x) {
    float y;
    asm("tanh.approx.f32 %0, %1;" : "=f"(y) : "f"(x));
    return y;
}
// sigmoid(0.01*p) via tanh identity: 1 MUFU instead of 2 dependent ones
__device__ __forceinline__ float sigmoid01(float p) {
    return fmaf(0.5f, tanh_approx(0.005f * p), 0.5f);
}
__device__ __forceinline__ float softplus_f(float z) {
    return __logf(1.f + __expf(z));
}

__global__ __launch_bounds__(NT, 1)
void voltage_kernel(const float* __restrict__ X, const float* __restrict__ SC,
                    const float* __restrict__ W1, const float* __restrict__ b1,
                    const float* __restrict__ W2, const float* __restrict__ b2,
                    float* __restrict__ out)
{
    __shared__ float sRed[32];
    __shared__ float sA[32];
    __shared__ float sB[32];
    __shared__ float sLastT[NT];   // each thread's t[EE-1]
    __shared__ float sLastI[NT];   // each thread's I[EE-1]
    __shared__ float sFirstI[NT];  // each thread's I[0]
    __shared__ float sTmean;
    __shared__ float sU10;

    const int b    = blockIdx.x;
    const int tid  = threadIdx.x;
    const int lane = tid & 31;
    const int wid  = tid >> 5;
    const int cs   = tid * EE;
    const float* __restrict__ Xb = X + (size_t)b * TT * 3;

    // ---------- phase 1: vectorized chunk load (12 x LDG.128 per thread) ----------
    float tA[EE], IA[EE];
    float tsum = 0.f;
    {
        const float4* __restrict__ p4 =
            reinterpret_cast<const float4*>(Xb + (size_t)cs * 3);
        float4 v[12];
        #pragma unroll
        for (int k = 0; k < 12; ++k) v[k] = __ldg(p4 + k);
        #pragma unroll
        for (int g = 0; g < 4; ++g) {
            float4 a0 = v[3 * g + 0], a1 = v[3 * g + 1], a2 = v[3 * g + 2];
            tA[4 * g + 0] = a0.x; IA[4 * g + 0] = a0.y; tsum += a0.z;
            tA[4 * g + 1] = a0.w; IA[4 * g + 1] = a1.x; tsum += a1.y;
            tA[4 * g + 2] = a1.z; IA[4 * g + 2] = a1.w; tsum += a2.x;
            tA[4 * g + 3] = a2.y; IA[4 * g + 3] = a2.z; tsum += a2.w;
        }
    }
    sLastT[tid]  = tA[EE - 1];
    sLastI[tid]  = IA[EE - 1];
    sFirstI[tid] = IA[0];

    // block reduce for Tmean (nanmean over NaN-free data == mean)
    #pragma unroll
    for (int o = 16; o > 0; o >>= 1) tsum += __shfl_down_sync(0xffffffffu, tsum, o);
    if (lane == 0) sRed[wid] = tsum;
    __syncthreads();
    if (tid < 32) {
        float v = (tid < NT / 32) ? sRed[tid] : 0.f;
        #pragma unroll
        for (int o = 16; o > 0; o >>= 1) v += __shfl_down_sync(0xffffffffu, v, o);
        if (tid == 0) sTmean = v * (1.f / (float)TT);
    }
    __syncthreads();
    const float Tmean = sTmean;
    const float Q  = __ldg(SC + 2 * b + 0);
    const float R0 = __ldg(SC + 2 * b + 1);

    // ---------- phase 2: per-thread local dSOC prefix (registers only) ----------
    float mA[EE];              // holds soc now; overwritten with base later
    float run = 0.f;
    {
        const float tprev = (tid > 0) ? sLastT[tid - 1] : 0.f;
        const float Iprev = (tid > 0) ? sLastI[tid - 1] : 0.f;
        if (tid > 0)
            run = (IA[0] + Iprev) * (tA[0] - tprev) * (1.f / 36000.f);
        mA[0] = run;
        #pragma unroll
        for (int e = 1; e < EE; ++e) {
            run += (IA[e] + IA[e - 1]) * (tA[e] - tA[e - 1]) * (1.f / 36000.f);
            mA[e] = run;
        }
    }
    // exclusive block scan of thread totals
    float inc = run;
    #pragma unroll
    for (int o = 1; o < 32; o <<= 1) {
        float y = __shfl_up_sync(0xffffffffu, inc, o);
        if (lane >= o) inc += y;
    }
    if (lane == 31) sRed[wid] = inc;
    __syncthreads();
    if (tid < 32) {
        float v = (tid < NT / 32) ? sRed[tid] : 0.f;
        #pragma unroll
        for (int o = 1; o < 32; o <<= 1) {
            float y = __shfl_up_sync(0xffffffffu, v, o);
            if (lane >= o) v += y;
        }
        sRed[tid] = v;   // inclusive warp totals
    }
    __syncthreads();
    const float warpOff = (wid > 0) ? sRed[wid - 1] : 0.f;
    const float socBase = Q * 0.2f + warpOff + (inc - run);

    // ---------- weights: fold constant MLP inputs (R0, Tmean per-batch consts) ----------
    float w10[6], c1r[6], w20[6], w21[6], w25[6], w26[6];
    #pragma unroll
    for (int j = 0; j < 6; ++j) {
        w10[j]    = __ldg(W1 + j);
        float w11 = __ldg(W1 + 6 + j);
        float w12 = __ldg(W1 + 12 + j);
        c1r[j] = fmaf(R0, w11, fmaf(Tmean, w12, __ldg(b1 + j)));
        w20[j] = __ldg(W2 + j * 7 + 0);
        w21[j] = __ldg(W2 + j * 7 + 1);
        w25[j] = __ldg(W2 + j * 7 + 5);
        w26[j] = __ldg(W2 + j * 7 + 6);
    }
    const float b20 = __ldg(b2 + 0), b21 = __ldg(b2 + 1);
    const float b25 = __ldg(b2 + 5), b26 = __ldg(b2 + 6);
    const float Inext = (tid < NT - 1) ? sFirstI[tid + 1] : 0.f;

    // ---------- phase 3: fully-unrolled MLP + OCV + affine transition ----------
    float aA[EE], bA[EE];
    float At = 1.f, Bt = 0.f;
    #pragma unroll
    for (int e = 0; e < EE; ++e) {
        float soc = socBase + mA[e];

        float h[6];
        #pragma unroll
        for (int j = 0; j < 6; ++j)
            h[j] = softplus_f(fmaf(soc, w10[j], c1r[j]));

        float p0 = b20, p1 = b21, p5 = b25, p6 = b26;
        #pragma unroll
        for (int j = 0; j < 6; ++j) {
            p0 = fmaf(h[j], w20[j], p0);
            p1 = fmaf(h[j], w21[j], p1);
            p5 = fmaf(h[j], w25[j], p5);
            p6 = fmaf(h[j], w26[j], p6);
        }
        float R1 = 0.04f * sigmoid01(p0);
        float C  = 1e-6f * sigmoid01(p1);
        float xx = fmaf(0.79764f, sigmoid01(p5), 0.04236f);
        float yy = fmaf(0.82504f, sigmoid01(p6), 0.023f);

        float Up = fmaf(fmaf(fmaf(fmaf(fmaf(-2.2166f, yy, 3.5146f), yy, -2.0843f),
                                 yy, 1.6225f), yy, -1.6518f), yy, 4.4167f)
                 - 4.f * __expf(fmaf(109.451f, yy, -100.006f));
        float Un = 0.063f + 0.8f * __expf(-75.f * (xx + 0.001f))
                 - 0.012f  * tanh_approx((xx - 0.127f) * 62.5f)
                 - 0.0118f * tanh_approx((xx - 0.155f) * 62.5f)
                 - 0.0035f * tanh_approx((xx - 0.22f)  * 50.f)
                 - 0.0095f * tanh_approx((xx - 0.19f)  * 76.923076923f)
                 - 0.0145f * tanh_approx((xx - 0.49f)  * 50.f)
                 - 0.08f   * tanh_approx((xx - 1.03f)  * 18.18181818f);

        float Ii = IA[e];
        if (e == 0 && tid == 0) {
            float p2 = __ldg(b2 + 2);
            #pragma unroll
            for (int j = 0; j < 6; ++j) p2 = fmaf(h[j], __ldg(W2 + j * 7 + 2), p2);
            float OCV_U = fmaf(0.75f, sigmoid01(p2), 0.05f);
            sU10 = -OCV_U - Ii * R0;
        }
        mA[e] = fmaf(Ii, R0, Up - Un);   // overwrite soc with base voltage

        float In1 = (e < EE - 1) ? IA[e + 1] : Inext;
        bool last = (tid == NT - 1) && (e == EE - 1);
        float eps = (In1 - Ii) * C;      // dt = diff of I (per reference)
        float a  = last ? 1.f : 1.f - eps;
        float bb = last ? 0.f : eps * R1 * Ii;
        aA[e] = a; bA[e] = bb;
        Bt = fmaf(a, Bt, bb);
        At = a * At;
    }

    // ---------- phase 4: block affine-pair scan (exclusive) ----------
    float Ai = At, Bi = Bt;
    #pragma unroll
    for (int o = 1; o < 32; o <<= 1) {
        float pA = __shfl_up_sync(0xffffffffu, Ai, o);
        float pB = __shfl_up_sync(0xffffffffu, Bi, o);
        if (lane >= o) { Bi = fmaf(Ai, pB, Bi); Ai = Ai * pA; }
    }
    if (lane == 31) { sA[wid] = Ai; sB[wid] = Bi; }
    __syncthreads();
    if (tid < 32) {
        float vA = (tid < NT / 32) ? sA[tid] : 1.f;
        float vB = (tid < NT / 32) ? sB[tid] : 0.f;
        #pragma unroll
        for (int o = 1; o < 32; o <<= 1) {
            float pA = __shfl_up_sync(0xffffffffu, vA, o);
            float pB = __shfl_up_sync(0xffffffffu, vB, o);
            if (lane >= o) { vB = fmaf(vA, pB, vB); vA = vA * pA; }
        }
        sA[tid] = vA; sB[tid] = vB;
    }
    __syncthreads();
    float offA = 1.f, offB = 0.f;
    if (wid > 0) { offA = sA[wid - 1]; offB = sB[wid - 1]; }
    float eA = __shfl_up_sync(0xffffffffu, Ai, 1);
    float eB = __shfl_up_sync(0xffffffffu, Bi, 1);
    if (lane == 0) { eA = 1.f; eB = 0.f; }
    float GA = eA * offA;
    float GB = fmaf(eA, offB, eB);
    float U1 = fmaf(GA, sU10, GB);

    // ---------- phase 5: emit with float4 stores ----------
    float4* __restrict__ o4 = reinterpret_cast<float4*>(out + (size_t)b * TT + cs);
    #pragma unroll
    for (int g = 0; g < 4; ++g) {
        float4 w;
        w.x = mA[4 * g + 0] + U1;  U1 = fmaf(aA[4 * g + 0], U1, bA[4 * g + 0]);
        w.y = mA[4 * g + 1] + U1;  U1 = fmaf(aA[4 * g + 1], U1, bA[4 * g + 1]);
        w.z = mA[4 * g + 2] + U1;  U1 = fmaf(aA[4 * g + 2], U1, bA[4 * g + 2]);
        w.w = mA[4 * g + 3] + U1;  U1 = fmaf(aA[4 * g + 3], U1, bA[4 * g + 3]);
        o4[g] = w;
    }
}

extern "C" void kernel_launch(void* const* d_in, const int* in_sizes, int n_in,
                              void* d_out, int out_size)
{
    const float* X  = (const float*)d_in[0];
    const float* SC = (const float*)d_in[1];
    const float* W1 = (const float*)d_in[2];
    const float* b1 = (const float*)d_in[3];
    const float* W2 = (const float*)d_in[4];
    const float* b2 = (const float*)d_in[5];
    float* out = (float*)d_out;

    int B = in_sizes[1] / 2;   // SC is (B, 2)
    voltage_kernel<<<B, NT>>>(X, SC, W1, b1, W2, b2, out);
}